// round 10
// baseline (speedup 1.0000x reference)
#include <cuda_runtime.h>
#include <math.h>
#include <float.h>

// ---------------------------------------------------------------------------
// Problem constants
// ---------------------------------------------------------------------------
#define B_     4
#define N_     2048
#define TOK    8192            // B_ * N_
#define DIM_   768
#define NH_    12
#define HD_    64
#define HID_   3072
#define QKVD_  2304            // 3 * DIM_
#define EPS_   1e-6f

// ---------------------------------------------------------------------------
// Scratch buffers (allocation-free: __device__ globals)
// ---------------------------------------------------------------------------
__device__ float g_h   [(size_t)TOK * DIM_];   // ln1(x)
__device__ float g_qkv [(size_t)TOK * QKVD_];  // qkv = h @ Wqkv^T + b
__device__ float g_attn[(size_t)TOK * DIM_];   // attention output (merged heads)
__device__ float g_x1  [(size_t)TOK * DIM_];   // x + proj(attn)
__device__ float g_h2  [(size_t)TOK * DIM_];   // ln2(x1)
__device__ float g_ffn [(size_t)TOK * HID_];   // gelu(fc1)

// ---------------------------------------------------------------------------
// LayerNorm: one block per row (768 = 256 * 3)
// ---------------------------------------------------------------------------
__device__ __forceinline__ float warp_sum(float v) {
#pragma unroll
    for (int off = 16; off >= 1; off >>= 1)
        v += __shfl_xor_sync(0xffffffffu, v, off);
    return v;
}

__global__ __launch_bounds__(256) void ln_kernel(
    const float* __restrict__ x,
    const float* __restrict__ g,
    const float* __restrict__ b,
    float* __restrict__ y)
{
    const int row = blockIdx.x;
    const int tid = threadIdx.x;
    const float* xr = x + (size_t)row * DIM_;
    float* yr = y + (size_t)row * DIM_;

    float v0 = xr[tid];
    float v1 = xr[tid + 256];
    float v2 = xr[tid + 512];

    float s  = v0 + v1 + v2;
    float s2 = v0 * v0 + v1 * v1 + v2 * v2;

    __shared__ float sm[16];
    s  = warp_sum(s);
    s2 = warp_sum(s2);
    const int w = tid >> 5, ln = tid & 31;
    if (ln == 0) { sm[w] = s; sm[8 + w] = s2; }
    __syncthreads();

    float ts = 0.f, ts2 = 0.f;
#pragma unroll
    for (int i = 0; i < 8; i++) { ts += sm[i]; ts2 += sm[8 + i]; }

    const float mu  = ts * (1.f / DIM_);
    const float var = ts2 * (1.f / DIM_) - mu * mu;
    const float inv = rsqrtf(var + EPS_);

    yr[tid]       = (v0 - mu) * inv * g[tid]       + b[tid];
    yr[tid + 256] = (v1 - mu) * inv * g[tid + 256] + b[tid + 256];
    yr[tid + 512] = (v2 - mu) * inv * g[tid + 512] + b[tid + 512];
}

// ---------------------------------------------------------------------------
// NT GEMM: C[M,N] = A[M,K] @ B[N,K]^T + bias (+ residual) (GELU optional)
// 128x128 tile, BK=8, 256 threads, 8x8 per thread.
// ---------------------------------------------------------------------------
template<bool GELU, bool RES>
__global__ __launch_bounds__(256) void gemm_nt(
    const float* __restrict__ A,
    const float* __restrict__ Bw,
    const float* __restrict__ bias,
    const float* __restrict__ res,
    float* __restrict__ C,
    int M, int N, int K)
{
    __shared__ float As[8][132];
    __shared__ float Bs[8][132];

    const int tid  = threadIdx.x;
    const int bm   = blockIdx.y * 128;
    const int bn   = blockIdx.x * 128;
    const int warp = tid >> 5, lane = tid & 31;
    const int wr = warp & 3;        // 4 warps along rows (32 rows each)
    const int wc = warp >> 2;       // 2 warps along cols (64 cols each)
    const int lr = lane >> 3;       // 4 lane-rows (8 rows each)
    const int lc = lane & 7;        // 8 lane-cols (8 cols each)
    const int row0 = wr * 32 + lr * 8;
    const int col0 = wc * 64 + lc * 8;

    const int ldr = tid >> 1;            // 0..127
    const int ldk = (tid & 1) * 4;       // 0 or 4
    const float* Ap = A  + (size_t)(bm + ldr) * K + ldk;
    const float* Bp = Bw + (size_t)(bn + ldr) * K + ldk;

    float acc[8][8];
#pragma unroll
    for (int i = 0; i < 8; i++)
#pragma unroll
        for (int j = 0; j < 8; j++) acc[i][j] = 0.f;

    float4 av = *(const float4*)Ap;
    float4 bv = *(const float4*)Bp;

    for (int k0 = 0; k0 < K; k0 += 8) {
        __syncthreads();
        As[ldk + 0][ldr] = av.x; As[ldk + 1][ldr] = av.y;
        As[ldk + 2][ldr] = av.z; As[ldk + 3][ldr] = av.w;
        Bs[ldk + 0][ldr] = bv.x; Bs[ldk + 1][ldr] = bv.y;
        Bs[ldk + 2][ldr] = bv.z; Bs[ldk + 3][ldr] = bv.w;
        __syncthreads();
        if (k0 + 8 < K) {
            av = *(const float4*)(Ap + k0 + 8);
            bv = *(const float4*)(Bp + k0 + 8);
        }
#pragma unroll
        for (int k = 0; k < 8; k++) {
            float4 a0 = *(const float4*)&As[k][row0];
            float4 a1 = *(const float4*)&As[k][row0 + 4];
            float4 b0 = *(const float4*)&Bs[k][col0];
            float4 b1 = *(const float4*)&Bs[k][col0 + 4];
            float ar[8] = {a0.x, a0.y, a0.z, a0.w, a1.x, a1.y, a1.z, a1.w};
            float br[8] = {b0.x, b0.y, b0.z, b0.w, b1.x, b1.y, b1.z, b1.w};
#pragma unroll
            for (int i = 0; i < 8; i++)
#pragma unroll
                for (int j = 0; j < 8; j++)
                    acc[i][j] += ar[i] * br[j];
        }
    }

#pragma unroll
    for (int i = 0; i < 8; i++) {
        const size_t row = (size_t)(bm + row0 + i);
        float* Cr = C + row * N + bn;
        const float* Rr = RES ? (res + row * N + bn) : nullptr;
#pragma unroll
        for (int j = 0; j < 8; j++) {
            const int col = col0 + j;
            float v = acc[i][j] + bias[bn + col];
            if (GELU) v = v * normcdff(v);   // exact GELU: x * Phi(x)
            if (RES)  v += Rr[col];
            Cr[col] = v;
        }
    }
}

// ---------------------------------------------------------------------------
// Flash attention: block = 64 queries x one (b,h); KV tiles of 64.
// qkv layout: [TOK, 2304], q/k/v at col offsets 0 / 768 / 1536, per-head +h*64.
// Output: [TOK, 768] with heads merged.
// ---------------------------------------------------------------------------
#define ATTN_PAD   68
#define ATTN_SMEM  (4 * 64 * ATTN_PAD * (int)sizeof(float))   // 69632 B

__global__ __launch_bounds__(256) void attn_kernel(
    const float* __restrict__ qkv,
    float* __restrict__ out)
{
    extern __shared__ float smem[];
    float* Qs = smem;                    // [64][68]
    float* Ks = Qs + 64 * ATTN_PAD;
    float* Vs = Ks + 64 * ATTN_PAD;
    float* Ps = Vs + 64 * ATTN_PAD;

    const int tid = threadIdx.x;
    const int ty = tid >> 4;             // 0..15  (query-row group)
    const int tx = tid & 15;             // 0..15  (key/dim-col group)
    const int bh = blockIdx.y;           // 0..47
    const int b  = bh / NH_;
    const int h  = bh % NH_;
    const int q0 = blockIdx.x * 64;
    const size_t rowbase = (size_t)b * N_;

    // tile loader mapping: 4 threads per row, 16 floats each
    const int lr = tid >> 2;             // 0..63
    const int lcl = (tid & 3) * 16;      // 0,16,32,48

    // ---- load + scale Q tile ----
    {
        const float* src = qkv + (rowbase + q0 + lr) * QKVD_ + h * HD_ + lcl;
        float* dst = &Qs[lr * ATTN_PAD + lcl];
#pragma unroll
        for (int c = 0; c < 4; c++) {
            float4 t = *(const float4*)(src + 4 * c);
            t.x *= 0.125f; t.y *= 0.125f; t.z *= 0.125f; t.w *= 0.125f;
            *(float4*)(dst + 4 * c) = t;
        }
    }

    float m[4], lsum[4], o[4][4];
#pragma unroll
    for (int i = 0; i < 4; i++) {
        m[i] = -FLT_MAX; lsum[i] = 0.f;
#pragma unroll
        for (int j = 0; j < 4; j++) o[i][j] = 0.f;
    }

    // prefetch KV tile 0
    float4 kreg[4], vreg[4];
    {
        const float* ksrc = qkv + (rowbase + lr) * QKVD_ + DIM_ + h * HD_ + lcl;
        const float* vsrc = qkv + (rowbase + lr) * QKVD_ + 2 * DIM_ + h * HD_ + lcl;
#pragma unroll
        for (int c = 0; c < 4; c++) {
            kreg[c] = *(const float4*)(ksrc + 4 * c);
            vreg[c] = *(const float4*)(vsrc + 4 * c);
        }
    }

    for (int t = 0; t < N_ / 64; t++) {
        __syncthreads();                 // prev PV done; Q ready at t=0
        {
            float* kd = &Ks[lr * ATTN_PAD + lcl];
            float* vd = &Vs[lr * ATTN_PAD + lcl];
#pragma unroll
            for (int c = 0; c < 4; c++) {
                *(float4*)(kd + 4 * c) = kreg[c];
                *(float4*)(vd + 4 * c) = vreg[c];
            }
        }
        __syncthreads();
        if (t + 1 < N_ / 64) {
            const size_t r = rowbase + (size_t)(t + 1) * 64 + lr;
            const float* ksrc = qkv + r * QKVD_ + DIM_ + h * HD_ + lcl;
            const float* vsrc = qkv + r * QKVD_ + 2 * DIM_ + h * HD_ + lcl;
#pragma unroll
            for (int c = 0; c < 4; c++) {
                kreg[c] = *(const float4*)(ksrc + 4 * c);
                vreg[c] = *(const float4*)(vsrc + 4 * c);
            }
        }

        // ---- S = (Q*scale) K^T : thread owns q=ty+16i, k=tx+16j ----
        float s[4][4];
#pragma unroll
        for (int i = 0; i < 4; i++)
#pragma unroll
            for (int j = 0; j < 4; j++) s[i][j] = 0.f;

#pragma unroll
        for (int d4 = 0; d4 < 16; d4++) {
            float4 qa[4], kb[4];
#pragma unroll
            for (int i = 0; i < 4; i++)
                qa[i] = *(const float4*)&Qs[(ty + 16 * i) * ATTN_PAD + 4 * d4];
#pragma unroll
            for (int j = 0; j < 4; j++)
                kb[j] = *(const float4*)&Ks[(tx + 16 * j) * ATTN_PAD + 4 * d4];
#pragma unroll
            for (int i = 0; i < 4; i++)
#pragma unroll
                for (int j = 0; j < 4; j++)
                    s[i][j] += qa[i].x * kb[j].x + qa[i].y * kb[j].y
                             + qa[i].z * kb[j].z + qa[i].w * kb[j].w;
        }

        // ---- online softmax (row reduce over 16 tx lanes) ----
#pragma unroll
        for (int i = 0; i < 4; i++) {
            float mx = fmaxf(fmaxf(s[i][0], s[i][1]), fmaxf(s[i][2], s[i][3]));
#pragma unroll
            for (int off = 8; off >= 1; off >>= 1)
                mx = fmaxf(mx, __shfl_xor_sync(0xffffffffu, mx, off));
            const float mn = fmaxf(m[i], mx);
            const float p0 = __expf(s[i][0] - mn);
            const float p1 = __expf(s[i][1] - mn);
            const float p2 = __expf(s[i][2] - mn);
            const float p3 = __expf(s[i][3] - mn);
            float ls = p0 + p1 + p2 + p3;
#pragma unroll
            for (int off = 8; off >= 1; off >>= 1)
                ls += __shfl_xor_sync(0xffffffffu, ls, off);
            const float alpha = __expf(m[i] - mn);
            m[i] = mn;
            lsum[i] = lsum[i] * alpha + ls;
            o[i][0] *= alpha; o[i][1] *= alpha; o[i][2] *= alpha; o[i][3] *= alpha;
            float* pr = &Ps[(ty + 16 * i) * ATTN_PAD + tx];
            pr[0] = p0; pr[16] = p1; pr[32] = p2; pr[48] = p3;
        }
        __syncthreads();

        // ---- O += P V : thread owns q=ty+16i, dd=tx+16j ----
#pragma unroll
        for (int k4 = 0; k4 < 16; k4++) {
            float pr[4][4];
#pragma unroll
            for (int i = 0; i < 4; i++) {
                float4 tt = *(const float4*)&Ps[(ty + 16 * i) * ATTN_PAD + 4 * k4];
                pr[i][0] = tt.x; pr[i][1] = tt.y; pr[i][2] = tt.z; pr[i][3] = tt.w;
            }
#pragma unroll
            for (int kk = 0; kk < 4; kk++) {
                float vb[4];
#pragma unroll
                for (int j = 0; j < 4; j++)
                    vb[j] = Vs[(4 * k4 + kk) * ATTN_PAD + tx + 16 * j];
#pragma unroll
                for (int i = 0; i < 4; i++)
#pragma unroll
                    for (int j = 0; j < 4; j++)
                        o[i][j] += pr[i][kk] * vb[j];
            }
        }
    }

    // ---- write O / l to merged-head output [TOK, 768] ----
#pragma unroll
    for (int i = 0; i < 4; i++) {
        const float invl = 1.f / lsum[i];
        float* orow = out + (rowbase + q0 + ty + 16 * i) * DIM_ + h * HD_ + tx;
#pragma unroll
        for (int j = 0; j < 4; j++)
            orow[16 * j] = o[i][j] * invl;
    }
}

// ---------------------------------------------------------------------------
// Launch
// ---------------------------------------------------------------------------
extern "C" void kernel_launch(void* const* d_in, const int* in_sizes, int n_in,
                              void* d_out, int out_size)
{
    const float* x      = (const float*)d_in[0];
    const float* ln1_g  = (const float*)d_in[1];
    const float* ln1_b  = (const float*)d_in[2];
    const float* qkv_w  = (const float*)d_in[3];
    const float* qkv_b  = (const float*)d_in[4];
    const float* proj_w = (const float*)d_in[5];
    const float* proj_b = (const float*)d_in[6];
    const float* ln2_g  = (const float*)d_in[7];
    const float* ln2_b  = (const float*)d_in[8];
    const float* fc1_w  = (const float*)d_in[9];
    const float* fc1_b  = (const float*)d_in[10];
    const float* fc2_w  = (const float*)d_in[11];
    const float* fc2_b  = (const float*)d_in[12];
    float* out = (float*)d_out;

    float *ph, *pqkv, *pattn, *px1, *ph2, *pffn;
    cudaGetSymbolAddress((void**)&ph,    g_h);
    cudaGetSymbolAddress((void**)&pqkv,  g_qkv);
    cudaGetSymbolAddress((void**)&pattn, g_attn);
    cudaGetSymbolAddress((void**)&px1,   g_x1);
    cudaGetSymbolAddress((void**)&ph2,   g_h2);
    cudaGetSymbolAddress((void**)&pffn,  g_ffn);

    cudaFuncSetAttribute(attn_kernel,
                         cudaFuncAttributeMaxDynamicSharedMemorySize, ATTN_SMEM);

    // 1. h = LN1(x)
    ln_kernel<<<TOK, 256>>>(x, ln1_g, ln1_b, ph);
    // 2. qkv = h @ Wqkv^T + b           [8192, 2304]
    gemm_nt<false, false><<<dim3(QKVD_ / 128, TOK / 128), 256>>>(
        ph, qkv_w, qkv_b, nullptr, pqkv, TOK, QKVD_, DIM_);
    // 3. attn = softmax(QK^T/8) V       [8192, 768]
    attn_kernel<<<dim3(N_ / 64, B_ * NH_), 256, ATTN_SMEM>>>(pqkv, pattn);
    // 4. x1 = x + attn @ Wproj^T + b
    gemm_nt<false, true><<<dim3(DIM_ / 128, TOK / 128), 256>>>(
        pattn, proj_w, proj_b, x, px1, TOK, DIM_, DIM_);
    // 5. h2 = LN2(x1)
    ln_kernel<<<TOK, 256>>>(px1, ln2_g, ln2_b, ph2);
    // 6. ffn = gelu(h2 @ Wfc1^T + b)    [8192, 3072]
    gemm_nt<true, false><<<dim3(HID_ / 128, TOK / 128), 256>>>(
        ph2, fc1_w, fc1_b, nullptr, pffn, TOK, HID_, DIM_);
    // 7. out = x1 + ffn @ Wfc2^T + b
    gemm_nt<false, true><<<dim3(DIM_ / 128, TOK / 128), 256>>>(
        pffn, fc2_w, fc2_b, px1, out, TOK, DIM_, HID_);
}

// round 11
// speedup vs baseline: 1.0009x; 1.0009x over previous
#include <cuda_runtime.h>
#include <math.h>
#include <float.h>

// ---------------------------------------------------------------------------
// Problem constants
// ---------------------------------------------------------------------------
#define B_     4
#define N_     2048
#define TOK    8192            // B_ * N_
#define DIM_   768
#define NH_    12
#define HD_    64
#define HID_   3072
#define QKVD_  2304            // 3 * DIM_
#define EPS_   1e-6f

// ---------------------------------------------------------------------------
// Scratch buffers (allocation-free: __device__ globals)
// ---------------------------------------------------------------------------
__device__ float g_h   [(size_t)TOK * DIM_];   // ln1(x)
__device__ float g_qkv [(size_t)TOK * QKVD_];  // qkv = h @ Wqkv^T + b
__device__ float g_attn[(size_t)TOK * DIM_];   // attention output (merged heads)
__device__ float g_x1  [(size_t)TOK * DIM_];   // x + proj(attn)
__device__ float g_h2  [(size_t)TOK * DIM_];   // ln2(x1)
__device__ float g_ffn [(size_t)TOK * HID_];   // gelu(fc1)

// ---------------------------------------------------------------------------
// LayerNorm: one block per row (768 = 256 * 3)
// ---------------------------------------------------------------------------
__device__ __forceinline__ float warp_sum(float v) {
#pragma unroll
    for (int off = 16; off >= 1; off >>= 1)
        v += __shfl_xor_sync(0xffffffffu, v, off);
    return v;
}

__global__ __launch_bounds__(256) void ln_kernel(
    const float* __restrict__ x,
    const float* __restrict__ g,
    const float* __restrict__ b,
    float* __restrict__ y)
{
    const int row = blockIdx.x;
    const int tid = threadIdx.x;
    const float* xr = x + (size_t)row * DIM_;
    float* yr = y + (size_t)row * DIM_;

    float v0 = xr[tid];
    float v1 = xr[tid + 256];
    float v2 = xr[tid + 512];

    float s  = v0 + v1 + v2;
    float s2 = v0 * v0 + v1 * v1 + v2 * v2;

    __shared__ float sm[16];
    s  = warp_sum(s);
    s2 = warp_sum(s2);
    const int w = tid >> 5, ln = tid & 31;
    if (ln == 0) { sm[w] = s; sm[8 + w] = s2; }
    __syncthreads();

    float ts = 0.f, ts2 = 0.f;
#pragma unroll
    for (int i = 0; i < 8; i++) { ts += sm[i]; ts2 += sm[8 + i]; }

    const float mu  = ts * (1.f / DIM_);
    const float var = ts2 * (1.f / DIM_) - mu * mu;
    const float inv = rsqrtf(var + EPS_);

    yr[tid]       = (v0 - mu) * inv * g[tid]       + b[tid];
    yr[tid + 256] = (v1 - mu) * inv * g[tid + 256] + b[tid + 256];
    yr[tid + 512] = (v2 - mu) * inv * g[tid + 512] + b[tid + 512];
}

// ---------------------------------------------------------------------------
// NT GEMM: C[M,N] = A[M,K] @ B[N,K]^T + bias (+ residual) (GELU optional)
// 128x128 tile, BK=8, 256 threads, 8x8 per thread.
// ---------------------------------------------------------------------------
template<bool GELU, bool RES>
__global__ __launch_bounds__(256) void gemm_nt(
    const float* __restrict__ A,
    const float* __restrict__ Bw,
    const float* __restrict__ bias,
    const float* __restrict__ res,
    float* __restrict__ C,
    int M, int N, int K)
{
    __shared__ float As[8][132];
    __shared__ float Bs[8][132];

    const int tid  = threadIdx.x;
    const int bm   = blockIdx.y * 128;
    const int bn   = blockIdx.x * 128;
    const int warp = tid >> 5, lane = tid & 31;
    const int wr = warp & 3;        // 4 warps along rows (32 rows each)
    const int wc = warp >> 2;       // 2 warps along cols (64 cols each)
    const int lr = lane >> 3;       // 4 lane-rows (8 rows each)
    const int lc = lane & 7;        // 8 lane-cols (8 cols each)
    const int row0 = wr * 32 + lr * 8;
    const int col0 = wc * 64 + lc * 8;

    const int ldr = tid >> 1;            // 0..127
    const int ldk = (tid & 1) * 4;       // 0 or 4
    const float* Ap = A  + (size_t)(bm + ldr) * K + ldk;
    const float* Bp = Bw + (size_t)(bn + ldr) * K + ldk;

    float acc[8][8];
#pragma unroll
    for (int i = 0; i < 8; i++)
#pragma unroll
        for (int j = 0; j < 8; j++) acc[i][j] = 0.f;

    float4 av = *(const float4*)Ap;
    float4 bv = *(const float4*)Bp;

    for (int k0 = 0; k0 < K; k0 += 8) {
        __syncthreads();
        As[ldk + 0][ldr] = av.x; As[ldk + 1][ldr] = av.y;
        As[ldk + 2][ldr] = av.z; As[ldk + 3][ldr] = av.w;
        Bs[ldk + 0][ldr] = bv.x; Bs[ldk + 1][ldr] = bv.y;
        Bs[ldk + 2][ldr] = bv.z; Bs[ldk + 3][ldr] = bv.w;
        __syncthreads();
        if (k0 + 8 < K) {
            av = *(const float4*)(Ap + k0 + 8);
            bv = *(const float4*)(Bp + k0 + 8);
        }
#pragma unroll
        for (int k = 0; k < 8; k++) {
            float4 a0 = *(const float4*)&As[k][row0];
            float4 a1 = *(const float4*)&As[k][row0 + 4];
            float4 b0 = *(const float4*)&Bs[k][col0];
            float4 b1 = *(const float4*)&Bs[k][col0 + 4];
            float ar[8] = {a0.x, a0.y, a0.z, a0.w, a1.x, a1.y, a1.z, a1.w};
            float br[8] = {b0.x, b0.y, b0.z, b0.w, b1.x, b1.y, b1.z, b1.w};
#pragma unroll
            for (int i = 0; i < 8; i++)
#pragma unroll
                for (int j = 0; j < 8; j++)
                    acc[i][j] += ar[i] * br[j];
        }
    }

#pragma unroll
    for (int i = 0; i < 8; i++) {
        const size_t row = (size_t)(bm + row0 + i);
        float* Cr = C + row * N + bn;
        const float* Rr = RES ? (res + row * N + bn) : nullptr;
#pragma unroll
        for (int j = 0; j < 8; j++) {
            const int col = col0 + j;
            float v = acc[i][j] + bias[bn + col];
            if (GELU) v = v * normcdff(v);   // exact GELU: x * Phi(x)
            if (RES)  v += Rr[col];
            Cr[col] = v;
        }
    }
}

// ---------------------------------------------------------------------------
// Flash attention: block = 64 queries x one (b,h); KV tiles of 64.
// qkv layout: [TOK, 2304], q/k/v at col offsets 0 / 768 / 1536, per-head +h*64.
// Output: [TOK, 768] with heads merged.
// ---------------------------------------------------------------------------
#define ATTN_PAD   68
#define ATTN_SMEM  (4 * 64 * ATTN_PAD * (int)sizeof(float))   // 69632 B

__global__ __launch_bounds__(256) void attn_kernel(
    const float* __restrict__ qkv,
    float* __restrict__ out)
{
    extern __shared__ float smem[];
    float* Qs = smem;                    // [64][68]
    float* Ks = Qs + 64 * ATTN_PAD;
    float* Vs = Ks + 64 * ATTN_PAD;
    float* Ps = Vs + 64 * ATTN_PAD;

    const int tid = threadIdx.x;
    const int ty = tid >> 4;             // 0..15  (query-row group)
    const int tx = tid & 15;             // 0..15  (key/dim-col group)
    const int bh = blockIdx.y;           // 0..47
    const int b  = bh / NH_;
    const int h  = bh % NH_;
    const int q0 = blockIdx.x * 64;
    const size_t rowbase = (size_t)b * N_;

    // tile loader mapping: 4 threads per row, 16 floats each
    const int lr = tid >> 2;             // 0..63
    const int lcl = (tid & 3) * 16;      // 0,16,32,48

    // ---- load + scale Q tile ----
    {
        const float* src = qkv + (rowbase + q0 + lr) * QKVD_ + h * HD_ + lcl;
        float* dst = &Qs[lr * ATTN_PAD + lcl];
#pragma unroll
        for (int c = 0; c < 4; c++) {
            float4 t = *(const float4*)(src + 4 * c);
            t.x *= 0.125f; t.y *= 0.125f; t.z *= 0.125f; t.w *= 0.125f;
            *(float4*)(dst + 4 * c) = t;
        }
    }

    float m[4], lsum[4], o[4][4];
#pragma unroll
    for (int i = 0; i < 4; i++) {
        m[i] = -FLT_MAX; lsum[i] = 0.f;
#pragma unroll
        for (int j = 0; j < 4; j++) o[i][j] = 0.f;
    }

    // prefetch KV tile 0
    float4 kreg[4], vreg[4];
    {
        const float* ksrc = qkv + (rowbase + lr) * QKVD_ + DIM_ + h * HD_ + lcl;
        const float* vsrc = qkv + (rowbase + lr) * QKVD_ + 2 * DIM_ + h * HD_ + lcl;
#pragma unroll
        for (int c = 0; c < 4; c++) {
            kreg[c] = *(const float4*)(ksrc + 4 * c);
            vreg[c] = *(const float4*)(vsrc + 4 * c);
        }
    }

    for (int t = 0; t < N_ / 64; t++) {
        __syncthreads();                 // prev PV done; Q ready at t=0
        {
            float* kd = &Ks[lr * ATTN_PAD + lcl];
            float* vd = &Vs[lr * ATTN_PAD + lcl];
#pragma unroll
            for (int c = 0; c < 4; c++) {
                *(float4*)(kd + 4 * c) = kreg[c];
                *(float4*)(vd + 4 * c) = vreg[c];
            }
        }
        __syncthreads();
        if (t + 1 < N_ / 64) {
            const size_t r = rowbase + (size_t)(t + 1) * 64 + lr;
            const float* ksrc = qkv + r * QKVD_ + DIM_ + h * HD_ + lcl;
            const float* vsrc = qkv + r * QKVD_ + 2 * DIM_ + h * HD_ + lcl;
#pragma unroll
            for (int c = 0; c < 4; c++) {
                kreg[c] = *(const float4*)(ksrc + 4 * c);
                vreg[c] = *(const float4*)(vsrc + 4 * c);
            }
        }

        // ---- S = (Q*scale) K^T : thread owns q=ty+16i, k=tx+16j ----
        float s[4][4];
#pragma unroll
        for (int i = 0; i < 4; i++)
#pragma unroll
            for (int j = 0; j < 4; j++) s[i][j] = 0.f;

#pragma unroll
        for (int d4 = 0; d4 < 16; d4++) {
            float4 qa[4], kb[4];
#pragma unroll
            for (int i = 0; i < 4; i++)
                qa[i] = *(const float4*)&Qs[(ty + 16 * i) * ATTN_PAD + 4 * d4];
#pragma unroll
            for (int j = 0; j < 4; j++)
                kb[j] = *(const float4*)&Ks[(tx + 16 * j) * ATTN_PAD + 4 * d4];
#pragma unroll
            for (int i = 0; i < 4; i++)
#pragma unroll
                for (int j = 0; j < 4; j++)
                    s[i][j] += qa[i].x * kb[j].x + qa[i].y * kb[j].y
                             + qa[i].z * kb[j].z + qa[i].w * kb[j].w;
        }

        // ---- online softmax (row reduce over 16 tx lanes) ----
#pragma unroll
        for (int i = 0; i < 4; i++) {
            float mx = fmaxf(fmaxf(s[i][0], s[i][1]), fmaxf(s[i][2], s[i][3]));
#pragma unroll
            for (int off = 8; off >= 1; off >>= 1)
                mx = fmaxf(mx, __shfl_xor_sync(0xffffffffu, mx, off));
            const float mn = fmaxf(m[i], mx);
            const float p0 = __expf(s[i][0] - mn);
            const float p1 = __expf(s[i][1] - mn);
            const float p2 = __expf(s[i][2] - mn);
            const float p3 = __expf(s[i][3] - mn);
            float ls = p0 + p1 + p2 + p3;
#pragma unroll
            for (int off = 8; off >= 1; off >>= 1)
                ls += __shfl_xor_sync(0xffffffffu, ls, off);
            const float alpha = __expf(m[i] - mn);
            m[i] = mn;
            lsum[i] = lsum[i] * alpha + ls;
            o[i][0] *= alpha; o[i][1] *= alpha; o[i][2] *= alpha; o[i][3] *= alpha;
            float* pr = &Ps[(ty + 16 * i) * ATTN_PAD + tx];
            pr[0] = p0; pr[16] = p1; pr[32] = p2; pr[48] = p3;
        }
        __syncthreads();

        // ---- O += P V : thread owns q=ty+16i, dd=tx+16j ----
#pragma unroll
        for (int k4 = 0; k4 < 16; k4++) {
            float pr[4][4];
#pragma unroll
            for (int i = 0; i < 4; i++) {
                float4 tt = *(const float4*)&Ps[(ty + 16 * i) * ATTN_PAD + 4 * k4];
                pr[i][0] = tt.x; pr[i][1] = tt.y; pr[i][2] = tt.z; pr[i][3] = tt.w;
            }
#pragma unroll
            for (int kk = 0; kk < 4; kk++) {
                float vb[4];
#pragma unroll
                for (int j = 0; j < 4; j++)
                    vb[j] = Vs[(4 * k4 + kk) * ATTN_PAD + tx + 16 * j];
#pragma unroll
                for (int i = 0; i < 4; i++)
#pragma unroll
                    for (int j = 0; j < 4; j++)
                        o[i][j] += pr[i][kk] * vb[j];
            }
        }
    }

    // ---- write O / l to merged-head output [TOK, 768] ----
#pragma unroll
    for (int i = 0; i < 4; i++) {
        const float invl = 1.f / lsum[i];
        float* orow = out + (rowbase + q0 + ty + 16 * i) * DIM_ + h * HD_ + tx;
#pragma unroll
        for (int j = 0; j < 4; j++)
            orow[16 * j] = o[i][j] * invl;
    }
}

// ---------------------------------------------------------------------------
// Launch
// ---------------------------------------------------------------------------
extern "C" void kernel_launch(void* const* d_in, const int* in_sizes, int n_in,
                              void* d_out, int out_size)
{
    const float* x      = (const float*)d_in[0];
    const float* ln1_g  = (const float*)d_in[1];
    const float* ln1_b  = (const float*)d_in[2];
    const float* qkv_w  = (const float*)d_in[3];
    const float* qkv_b  = (const float*)d_in[4];
    const float* proj_w = (const float*)d_in[5];
    const float* proj_b = (const float*)d_in[6];
    const float* ln2_g  = (const float*)d_in[7];
    const float* ln2_b  = (const float*)d_in[8];
    const float* fc1_w  = (const float*)d_in[9];
    const float* fc1_b  = (const float*)d_in[10];
    const float* fc2_w  = (const float*)d_in[11];
    const float* fc2_b  = (const float*)d_in[12];
    float* out = (float*)d_out;

    float *ph, *pqkv, *pattn, *px1, *ph2, *pffn;
    cudaGetSymbolAddress((void**)&ph,    g_h);
    cudaGetSymbolAddress((void**)&pqkv,  g_qkv);
    cudaGetSymbolAddress((void**)&pattn, g_attn);
    cudaGetSymbolAddress((void**)&px1,   g_x1);
    cudaGetSymbolAddress((void**)&ph2,   g_h2);
    cudaGetSymbolAddress((void**)&pffn,  g_ffn);

    cudaFuncSetAttribute(attn_kernel,
                         cudaFuncAttributeMaxDynamicSharedMemorySize, ATTN_SMEM);

    // 1. h = LN1(x)
    ln_kernel<<<TOK, 256>>>(x, ln1_g, ln1_b, ph);
    // 2. qkv = h @ Wqkv^T + b           [8192, 2304]
    gemm_nt<false, false><<<dim3(QKVD_ / 128, TOK / 128), 256>>>(
        ph, qkv_w, qkv_b, nullptr, pqkv, TOK, QKVD_, DIM_);
    // 3. attn = softmax(QK^T/8) V       [8192, 768]
    attn_kernel<<<dim3(N_ / 64, B_ * NH_), 256, ATTN_SMEM>>>(pqkv, pattn);
    // 4. x1 = x + attn @ Wproj^T + b
    gemm_nt<false, true><<<dim3(DIM_ / 128, TOK / 128), 256>>>(
        pattn, proj_w, proj_b, x, px1, TOK, DIM_, DIM_);
    // 5. h2 = LN2(x1)
    ln_kernel<<<TOK, 256>>>(px1, ln2_g, ln2_b, ph2);
    // 6. ffn = gelu(h2 @ Wfc1^T + b)    [8192, 3072]
    gemm_nt<true, false><<<dim3(HID_ / 128, TOK / 128), 256>>>(
        ph2, fc1_w, fc1_b, nullptr, pffn, TOK, HID_, DIM_);
    // 7. out = x1 + ffn @ Wfc2^T + b
    gemm_nt<false, true><<<dim3(DIM_ / 128, TOK / 128), 256>>>(
        pffn, fc2_w, fc2_b, px1, out, TOK, DIM_, HID_);
}